// round 1
// baseline (speedup 1.0000x reference)
#include <cuda_runtime.h>
#include <cuda_bf16.h>

#define NN 30000
#define EE 480000
#define HSTR 288      // hcat row stride (max K)
#define FD 256        // ft row width (H*64)

// ---------------- scratch (device globals; no allocs allowed) ----------------
__device__ float g_hcat[NN * HSTR];   // [h | pe] per layer, stride 288
__device__ float g_ft[NN * FD];       // per-layer transformed features
__device__ float g_a1[NN * 4];
__device__ float g_a2[NN * 4];
__device__ int   g_cnt[NN];           // counts, then cursor
__device__ int   g_off[NN + 1];       // CSR offsets by dst
__device__ int   g_csr_src[EE];       // src id per CSR slot

// ---------------- CSR build ----------------
__global__ void k_zero_cnt() {
    int i = blockIdx.x * blockDim.x + threadIdx.x;
    if (i < NN) g_cnt[i] = 0;
}

__global__ void k_count(const int* __restrict__ dst) {
    int e = blockIdx.x * blockDim.x + threadIdx.x;
    if (e < EE) atomicAdd(&g_cnt[dst[e]], 1);
}

// single-block exclusive scan over g_cnt -> g_off (and cursor init in g_cnt)
__global__ void k_scan() {
    __shared__ int warp_sums[32];
    __shared__ int s_carry;
    int tid = threadIdx.x;
    int lane = tid & 31, wid = tid >> 5;
    if (tid == 0) s_carry = 0;
    __syncthreads();
    for (int base = 0; base < NN; base += 1024) {
        int i = base + tid;
        int v = (i < NN) ? g_cnt[i] : 0;
        int x = v;
        #pragma unroll
        for (int d = 1; d < 32; d <<= 1) {
            int y = __shfl_up_sync(0xffffffffu, x, d);
            if (lane >= d) x += y;
        }
        if (lane == 31) warp_sums[wid] = x;
        __syncthreads();
        if (wid == 0) {
            int s = warp_sums[lane];
            #pragma unroll
            for (int d = 1; d < 32; d <<= 1) {
                int y = __shfl_up_sync(0xffffffffu, s, d);
                if (lane >= d) s += y;
            }
            warp_sums[lane] = s;
        }
        __syncthreads();
        int carry = s_carry;
        int excl = x - v + (wid > 0 ? warp_sums[wid - 1] : 0);
        if (i < NN) {
            g_off[i] = carry + excl;
            g_cnt[i] = carry + excl;   // cursor
        }
        int chunk_total = warp_sums[31];
        __syncthreads();
        if (tid == 0) s_carry = carry + chunk_total;
        __syncthreads();
    }
    if (threadIdx.x == 0) g_off[NN] = s_carry;
}

__global__ void k_place(const int* __restrict__ src, const int* __restrict__ dst) {
    int e = blockIdx.x * blockDim.x + threadIdx.x;
    if (e < EE) {
        int p = atomicAdd(&g_cnt[dst[e]], 1);
        g_csr_src[p] = src[e];
    }
}

// ---------------- hcat assembly ----------------
__global__ void k_copy_feat(const float* __restrict__ f) {
    int i = blockIdx.x * blockDim.x + threadIdx.x;   // over NN*128
    if (i < NN * 128) {
        int n = i >> 7, c = i & 127;
        g_hcat[n * HSTR + c] = f[i];
    }
}

__global__ void k_fill_pe(const float* __restrict__ pe, const int* __restrict__ pos, int col0) {
    int i = blockIdx.x * blockDim.x + threadIdx.x;   // over NN*32
    if (i < NN * 32) {
        int n = i >> 5, c = i & 31;
        g_hcat[n * HSTR + col0 + c] = pe[pos[n] * 32 + c];
    }
}

// ---------------- GEMM: g_ft = g_hcat[:, :K] @ W  (W row-major [K,256]) ----------------
__global__ void k_gemm(const float* __restrict__ W, int K) {
    __shared__ float As[16][65];
    __shared__ float Bs[16][64];
    int bm = blockIdx.y * 64;
    int bn = blockIdx.x * 64;
    int tid = threadIdx.x;
    int tx = tid & 15, ty = tid >> 4;
    float c[4][4] = {};
    for (int k0 = 0; k0 < K; k0 += 16) {
        #pragma unroll
        for (int i = tid; i < 64 * 16; i += 256) {
            int r = i >> 4, cc = i & 15;
            int row = bm + r;
            As[cc][r] = (row < NN) ? g_hcat[row * HSTR + k0 + cc] : 0.f;
        }
        #pragma unroll
        for (int i = tid; i < 16 * 64; i += 256) {
            int kk = i >> 6, nn = i & 63;
            Bs[kk][nn] = W[(k0 + kk) * 256 + bn + nn];
        }
        __syncthreads();
        #pragma unroll
        for (int kk = 0; kk < 16; kk++) {
            float a[4], b[4];
            #pragma unroll
            for (int i = 0; i < 4; i++) a[i] = As[kk][ty * 4 + i];
            #pragma unroll
            for (int j = 0; j < 4; j++) b[j] = Bs[kk][tx * 4 + j];
            #pragma unroll
            for (int i = 0; i < 4; i++)
                #pragma unroll
                for (int j = 0; j < 4; j++)
                    c[i][j] += a[i] * b[j];
        }
        __syncthreads();
    }
    #pragma unroll
    for (int i = 0; i < 4; i++) {
        int row = bm + ty * 4 + i;
        if (row < NN) {
            #pragma unroll
            for (int j = 0; j < 4; j++)
                g_ft[row * FD + bn + tx * 4 + j] = c[i][j];
        }
    }
}

// ---------------- attention logits a1,a2: one warp per (node, head) ----------------
__global__ void k_attn(const float* __restrict__ al, const float* __restrict__ ar) {
    int gw = (blockIdx.x * blockDim.x + threadIdx.x) >> 5;
    int lane = threadIdx.x & 31;
    if (gw >= NN * 4) return;
    int n = gw >> 2, h = gw & 3;
    const float* f = g_ft + n * FD + h * 64;
    float v0 = f[lane], v1 = f[lane + 32];
    float l0 = al[h * 64 + lane], l1 = al[h * 64 + lane + 32];
    float r0 = ar[h * 64 + lane], r1 = ar[h * 64 + lane + 32];
    float s1 = v0 * l0 + v1 * l1;
    float s2 = v0 * r0 + v1 * r1;
    #pragma unroll
    for (int d = 16; d; d >>= 1) {
        s1 += __shfl_xor_sync(0xffffffffu, s1, d);
        s2 += __shfl_xor_sync(0xffffffffu, s2, d);
    }
    if (lane == 0) {
        g_a1[n * 4 + h] = s1;
        g_a2[n * 4 + h] = s2;
    }
}

// ---------------- edge phase: one warp per destination node ----------------
// lane covers flattened dims [lane*8, lane*8+8): head = lane>>3, within-head dims (lane&7)*8..
__global__ void k_edge(float* __restrict__ out, int final_layer) {
    int gw = (blockIdx.x * blockDim.x + threadIdx.x) >> 5;
    int lane = threadIdx.x & 31;
    if (gw >= NN) return;
    int n = gw;
    int h = lane >> 3;
    float a2h = g_a2[n * 4 + h];
    int beg = g_off[n], end = g_off[n + 1];

    // pass 1: per-head max (every lane sees every edge)
    float m = -1e30f;
    for (int i = beg; i < end; i++) {
        int s = g_csr_src[i];
        float e = g_a1[s * 4 + h] + a2h;
        e = e > 0.f ? e : 0.2f * e;
        m = fmaxf(m, e);
    }
    // pass 2: softmax denominator
    float ssum = 0.f;
    for (int i = beg; i < end; i++) {
        int s = g_csr_src[i];
        float e = g_a1[s * 4 + h] + a2h;
        e = e > 0.f ? e : 0.2f * e;
        ssum += __expf(e - m);
    }
    float inv = ssum > 0.f ? 1.0f / ssum : 0.f;

    // pass 3: weighted gather-accumulate of ft[src]
    float acc[8] = {0, 0, 0, 0, 0, 0, 0, 0};
    for (int i = beg; i < end; i++) {
        int s = g_csr_src[i];
        float e = g_a1[s * 4 + h] + a2h;
        e = e > 0.f ? e : 0.2f * e;
        float alpha = __expf(e - m) * inv;
        const float4* p = (const float4*)(g_ft + s * FD + lane * 8);
        float4 u = p[0], w = p[1];
        acc[0] += u.x * alpha; acc[1] += u.y * alpha;
        acc[2] += u.z * alpha; acc[3] += u.w * alpha;
        acc[4] += w.x * alpha; acc[5] += w.y * alpha;
        acc[6] += w.z * alpha; acc[7] += w.w * alpha;
    }

    if (final_layer) {
        // mean over heads: lanes l, l^8, l^16, l^24 hold same within-head dims
        #pragma unroll
        for (int j = 0; j < 8; j++) {
            acc[j] += __shfl_xor_sync(0xffffffffu, acc[j], 8);
            acc[j] += __shfl_xor_sync(0xffffffffu, acc[j], 16);
        }
        if (lane < 8) {
            #pragma unroll
            for (int j = 0; j < 8; j++)
                out[n * 64 + lane * 8 + j] = acc[j] * 0.25f;
        }
    } else {
        float* d = g_hcat + n * HSTR + lane * 8;
        #pragma unroll
        for (int j = 0; j < 8; j++) {
            float x = acc[j];
            d[j] = x > 0.f ? x : expm1f(x);   // ELU
        }
    }
}

// ---------------- launcher ----------------
extern "C" void kernel_launch(void* const* d_in, const int* in_sizes, int n_in,
                              void* d_out, int out_size) {
    const float* features = (const float*)d_in[0];
    const float* W0  = (const float*)d_in[1];
    const float* al0 = (const float*)d_in[2];
    const float* ar0 = (const float*)d_in[3];
    const float* pe0 = (const float*)d_in[4];
    const float* W1  = (const float*)d_in[5];
    const float* al1 = (const float*)d_in[6];
    const float* ar1 = (const float*)d_in[7];
    const float* pe1 = (const float*)d_in[8];
    const float* W2  = (const float*)d_in[9];
    const float* al2 = (const float*)d_in[10];
    const float* ar2 = (const float*)d_in[11];
    const float* pe2 = (const float*)d_in[12];
    const int* src = (const int*)d_in[13];
    const int* dst = (const int*)d_in[14];
    const int* pos = (const int*)d_in[15];
    float* out = (float*)d_out;

    // CSR build (by destination)
    k_zero_cnt<<<(NN + 255) / 256, 256>>>();
    k_count<<<(EE + 255) / 256, 256>>>(dst);
    k_scan<<<1, 1024>>>();
    k_place<<<(EE + 255) / 256, 256>>>(src, dst);

    // layer-0 input assembly
    k_copy_feat<<<(NN * 128 + 255) / 256, 256>>>(features);
    k_fill_pe<<<(NN * 32 + 255) / 256, 256>>>(pe0, pos, 128);

    dim3 ggrid(256 / 64, (NN + 63) / 64);
    int attn_blocks = (NN * 4 + 7) / 8;   // 8 warps per 256-thread block
    int edge_blocks = (NN + 7) / 8;

    // layer 0
    k_gemm<<<ggrid, 256>>>(W0, 160);
    k_attn<<<attn_blocks, 256>>>(al0, ar0);
    k_edge<<<edge_blocks, 256>>>(out, 0);
    k_fill_pe<<<(NN * 32 + 255) / 256, 256>>>(pe1, pos, 256);

    // layer 1
    k_gemm<<<ggrid, 256>>>(W1, 288);
    k_attn<<<attn_blocks, 256>>>(al1, ar1);
    k_edge<<<edge_blocks, 256>>>(out, 0);
    k_fill_pe<<<(NN * 32 + 255) / 256, 256>>>(pe2, pos, 256);

    // layer 2 (output: mean over heads)
    k_gemm<<<ggrid, 256>>>(W2, 288);
    k_attn<<<attn_blocks, 256>>>(al2, ar2);
    k_edge<<<edge_blocks, 256>>>(out, 1);
}

// round 2
// speedup vs baseline: 1.8369x; 1.8369x over previous
#include <cuda_runtime.h>
#include <cuda_bf16.h>
#include <cstdint>

#define NN 30000
#define EE 480000
#define HSTR 288      // hcat row stride (max K)
#define FD 256        // ft row width (H*64)

// ---------------- scratch (device globals; no allocs allowed) ----------------
__device__ float g_hcat[NN * HSTR];   // [h | pe] per layer, stride 288
__device__ float g_ft[NN * FD];       // per-layer transformed features
__device__ float g_a1[NN * 4];
__device__ float g_a2[NN * 4];
__device__ int   g_cnt[NN];           // counts, then cursor
__device__ int   g_off[NN + 1];       // CSR offsets by dst
__device__ int   g_csr_src[EE];       // src id per CSR slot

// ---------------- CSR build ----------------
__global__ void k_zero_cnt() {
    int i = blockIdx.x * blockDim.x + threadIdx.x;
    if (i < NN) g_cnt[i] = 0;
}

__global__ void k_count(const int* __restrict__ dst) {
    int e = blockIdx.x * blockDim.x + threadIdx.x;
    if (e < EE) atomicAdd(&g_cnt[dst[e]], 1);
}

__global__ void k_scan() {
    __shared__ int warp_sums[32];
    __shared__ int s_carry;
    int tid = threadIdx.x;
    int lane = tid & 31, wid = tid >> 5;
    if (tid == 0) s_carry = 0;
    __syncthreads();
    for (int base = 0; base < NN; base += 1024) {
        int i = base + tid;
        int v = (i < NN) ? g_cnt[i] : 0;
        int x = v;
        #pragma unroll
        for (int d = 1; d < 32; d <<= 1) {
            int y = __shfl_up_sync(0xffffffffu, x, d);
            if (lane >= d) x += y;
        }
        if (lane == 31) warp_sums[wid] = x;
        __syncthreads();
        if (wid == 0) {
            int s = warp_sums[lane];
            #pragma unroll
            for (int d = 1; d < 32; d <<= 1) {
                int y = __shfl_up_sync(0xffffffffu, s, d);
                if (lane >= d) s += y;
            }
            warp_sums[lane] = s;
        }
        __syncthreads();
        int carry = s_carry;
        int excl = x - v + (wid > 0 ? warp_sums[wid - 1] : 0);
        if (i < NN) {
            g_off[i] = carry + excl;
            g_cnt[i] = carry + excl;
        }
        int chunk_total = warp_sums[31];
        __syncthreads();
        if (tid == 0) s_carry = carry + chunk_total;
        __syncthreads();
    }
    if (threadIdx.x == 0) g_off[NN] = s_carry;
}

__global__ void k_place(const int* __restrict__ src, const int* __restrict__ dst) {
    int e = blockIdx.x * blockDim.x + threadIdx.x;
    if (e < EE) {
        int p = atomicAdd(&g_cnt[dst[e]], 1);
        g_csr_src[p] = src[e];
    }
}

// ---------------- hcat assembly ----------------
__global__ void k_copy_feat(const float* __restrict__ f) {
    int i = blockIdx.x * blockDim.x + threadIdx.x;
    if (i < NN * 128) {
        int n = i >> 7, c = i & 127;
        g_hcat[n * HSTR + c] = f[i];
    }
}

__global__ void k_fill_pe(const float* __restrict__ pe, const int* __restrict__ pos, int col0) {
    int i = blockIdx.x * blockDim.x + threadIdx.x;
    if (i < NN * 32) {
        int n = i >> 5, c = i & 31;
        g_hcat[n * HSTR + col0 + c] = pe[pos[n] * 32 + c];
    }
}

// ---------------- TF32 tensor-core GEMM: g_ft = g_hcat[:, :K] @ W ----------------
// W row-major [K, 256]. Block tile 128x128, BK=16, 8 warps (4 M x 2 N),
// warp tile 32x64 -> 2x8 m16n8k8 mma tiles. Smem stride 136 words makes
// fragment loads bank-conflict-free (136 % 32 == 8).
#define BM 128
#define BN 128
#define BK 16
#define SSTR 136

__device__ __forceinline__ uint32_t f2tf32(float v) {
    uint32_t t;
    asm("cvt.rna.tf32.f32 %0, %1;" : "=r"(t) : "f"(v));
    return t;
}

__global__ __launch_bounds__(256, 2) void k_gemm_tf32(const float* __restrict__ W, int K) {
    __shared__ uint32_t As[BK * SSTR];   // As[k][m]
    __shared__ uint32_t Bs[BK * SSTR];   // Bs[k][n]
    int bm = blockIdx.y * BM;
    int bn = blockIdx.x * BN;
    int tid = threadIdx.x;
    int lane = tid & 31, warp = tid >> 5;
    int warpM = warp & 3, warpN = warp >> 2;     // 4 x 2
    int gid = lane >> 2, tig = lane & 3;         // octet row / quad col

    float c[2][8][4];
    #pragma unroll
    for (int mt = 0; mt < 2; mt++)
        #pragma unroll
        for (int nt = 0; nt < 8; nt++)
            #pragma unroll
            for (int q = 0; q < 4; q++) c[mt][nt][q] = 0.f;

    // A-load indices: 8 elements/thread, k fastest for coalescing
    int a_m = tid >> 4;              // 0..15, step +16 per iter (8 iters)
    int a_k = tid & 15;
    // B-load indices
    int b_n = tid & 127;
    int b_k = tid >> 7;              // 0..1, step +2 per iter (8 iters)

    // prologue: tile 0 straight to smem
    #pragma unroll
    for (int it = 0; it < 8; it++) {
        int m = a_m + it * 16;
        int row = bm + m;
        float v = (row < NN) ? g_hcat[row * HSTR + a_k] : 0.f;
        As[a_k * SSTR + m] = f2tf32(v);
    }
    #pragma unroll
    for (int it = 0; it < 8; it++) {
        int kk = b_k + it * 2;
        Bs[kk * SSTR + b_n] = f2tf32(W[kk * 256 + bn + b_n]);
    }
    __syncthreads();

    for (int k0 = 0; k0 < K; k0 += BK) {
        int kn = k0 + BK;
        float regA[8], regB[8];
        if (kn < K) {
            #pragma unroll
            for (int it = 0; it < 8; it++) {
                int row = bm + a_m + it * 16;
                regA[it] = (row < NN) ? g_hcat[row * HSTR + kn + a_k] : 0.f;
            }
            #pragma unroll
            for (int it = 0; it < 8; it++) {
                int kk = b_k + it * 2;
                regB[it] = W[(kn + kk) * 256 + bn + b_n];
            }
        }

        // compute this tile
        #pragma unroll
        for (int ks = 0; ks < BK; ks += 8) {
            uint32_t a[2][4], b[8][2];
            #pragma unroll
            for (int mt = 0; mt < 2; mt++) {
                int m0 = warpM * 32 + mt * 16 + gid;
                a[mt][0] = As[(ks + tig) * SSTR + m0];
                a[mt][1] = As[(ks + tig) * SSTR + m0 + 8];
                a[mt][2] = As[(ks + tig + 4) * SSTR + m0];
                a[mt][3] = As[(ks + tig + 4) * SSTR + m0 + 8];
            }
            #pragma unroll
            for (int nt = 0; nt < 8; nt++) {
                int n0 = warpN * 64 + nt * 8 + gid;
                b[nt][0] = Bs[(ks + tig) * SSTR + n0];
                b[nt][1] = Bs[(ks + tig + 4) * SSTR + n0];
            }
            #pragma unroll
            for (int mt = 0; mt < 2; mt++)
                #pragma unroll
                for (int nt = 0; nt < 8; nt++)
                    asm volatile(
                        "mma.sync.aligned.m16n8k8.row.col.f32.tf32.tf32.f32 "
                        "{%0,%1,%2,%3}, {%4,%5,%6,%7}, {%8,%9}, {%0,%1,%2,%3};"
                        : "+f"(c[mt][nt][0]), "+f"(c[mt][nt][1]),
                          "+f"(c[mt][nt][2]), "+f"(c[mt][nt][3])
                        : "r"(a[mt][0]), "r"(a[mt][1]), "r"(a[mt][2]), "r"(a[mt][3]),
                          "r"(b[nt][0]), "r"(b[nt][1]));
        }
        __syncthreads();
        if (kn < K) {
            #pragma unroll
            for (int it = 0; it < 8; it++)
                As[a_k * SSTR + a_m + it * 16] = f2tf32(regA[it]);
            #pragma unroll
            for (int it = 0; it < 8; it++)
                Bs[(b_k + it * 2) * SSTR + b_n] = f2tf32(regB[it]);
        }
        __syncthreads();
    }

    // epilogue
    #pragma unroll
    for (int mt = 0; mt < 2; mt++) {
        int row0 = bm + warpM * 32 + mt * 16 + gid;
        int row1 = row0 + 8;
        #pragma unroll
        for (int nt = 0; nt < 8; nt++) {
            int col = bn + warpN * 64 + nt * 8 + tig * 2;
            if (row0 < NN)
                *(float2*)(g_ft + row0 * FD + col) = make_float2(c[mt][nt][0], c[mt][nt][1]);
            if (row1 < NN)
                *(float2*)(g_ft + row1 * FD + col) = make_float2(c[mt][nt][2], c[mt][nt][3]);
        }
    }
}

// ---------------- attention logits a1,a2: one warp per (node, head) ----------------
__global__ void k_attn(const float* __restrict__ al, const float* __restrict__ ar) {
    int gw = (blockIdx.x * blockDim.x + threadIdx.x) >> 5;
    int lane = threadIdx.x & 31;
    if (gw >= NN * 4) return;
    int n = gw >> 2, h = gw & 3;
    const float* f = g_ft + n * FD + h * 64;
    float v0 = f[lane], v1 = f[lane + 32];
    float l0 = al[h * 64 + lane], l1 = al[h * 64 + lane + 32];
    float r0 = ar[h * 64 + lane], r1 = ar[h * 64 + lane + 32];
    float s1 = v0 * l0 + v1 * l1;
    float s2 = v0 * r0 + v1 * r1;
    #pragma unroll
    for (int d = 16; d; d >>= 1) {
        s1 += __shfl_xor_sync(0xffffffffu, s1, d);
        s2 += __shfl_xor_sync(0xffffffffu, s2, d);
    }
    if (lane == 0) {
        g_a1[n * 4 + h] = s1;
        g_a2[n * 4 + h] = s2;
    }
}

// ---------------- edge phase: one warp per destination node ----------------
__global__ void k_edge(float* __restrict__ out, int final_layer) {
    int gw = (blockIdx.x * blockDim.x + threadIdx.x) >> 5;
    int lane = threadIdx.x & 31;
    if (gw >= NN) return;
    int n = gw;
    int h = lane >> 3;
    float a2h = g_a2[n * 4 + h];
    int beg = g_off[n], end = g_off[n + 1];

    float m = -1e30f;
    for (int i = beg; i < end; i++) {
        int s = g_csr_src[i];
        float e = g_a1[s * 4 + h] + a2h;
        e = e > 0.f ? e : 0.2f * e;
        m = fmaxf(m, e);
    }
    float ssum = 0.f;
    for (int i = beg; i < end; i++) {
        int s = g_csr_src[i];
        float e = g_a1[s * 4 + h] + a2h;
        e = e > 0.f ? e : 0.2f * e;
        ssum += __expf(e - m);
    }
    float inv = ssum > 0.f ? 1.0f / ssum : 0.f;

    float acc[8] = {0, 0, 0, 0, 0, 0, 0, 0};
    for (int i = beg; i < end; i++) {
        int s = g_csr_src[i];
        float e = g_a1[s * 4 + h] + a2h;
        e = e > 0.f ? e : 0.2f * e;
        float alpha = __expf(e - m) * inv;
        const float4* p = (const float4*)(g_ft + s * FD + lane * 8);
        float4 u = p[0], w = p[1];
        acc[0] += u.x * alpha; acc[1] += u.y * alpha;
        acc[2] += u.z * alpha; acc[3] += u.w * alpha;
        acc[4] += w.x * alpha; acc[5] += w.y * alpha;
        acc[6] += w.z * alpha; acc[7] += w.w * alpha;
    }

    if (final_layer) {
        #pragma unroll
        for (int j = 0; j < 8; j++) {
            acc[j] += __shfl_xor_sync(0xffffffffu, acc[j], 8);
            acc[j] += __shfl_xor_sync(0xffffffffu, acc[j], 16);
        }
        if (lane < 8) {
            #pragma unroll
            for (int j = 0; j < 8; j++)
                out[n * 64 + lane * 8 + j] = acc[j] * 0.25f;
        }
    } else {
        float* d = g_hcat + n * HSTR + lane * 8;
        #pragma unroll
        for (int j = 0; j < 8; j++) {
            float x = acc[j];
            d[j] = x > 0.f ? x : expm1f(x);   // ELU
        }
    }
}

// ---------------- launcher ----------------
extern "C" void kernel_launch(void* const* d_in, const int* in_sizes, int n_in,
                              void* d_out, int out_size) {
    const float* features = (const float*)d_in[0];
    const float* W0  = (const float*)d_in[1];
    const float* al0 = (const float*)d_in[2];
    const float* ar0 = (const float*)d_in[3];
    const float* pe0 = (const float*)d_in[4];
    const float* W1  = (const float*)d_in[5];
    const float* al1 = (const float*)d_in[6];
    const float* ar1 = (const float*)d_in[7];
    const float* pe1 = (const float*)d_in[8];
    const float* W2  = (const float*)d_in[9];
    const float* al2 = (const float*)d_in[10];
    const float* ar2 = (const float*)d_in[11];
    const float* pe2 = (const float*)d_in[12];
    const int* src = (const int*)d_in[13];
    const int* dst = (const int*)d_in[14];
    const int* pos = (const int*)d_in[15];
    float* out = (float*)d_out;

    k_zero_cnt<<<(NN + 255) / 256, 256>>>();
    k_count<<<(EE + 255) / 256, 256>>>(dst);
    k_scan<<<1, 1024>>>();
    k_place<<<(EE + 255) / 256, 256>>>(src, dst);

    k_copy_feat<<<(NN * 128 + 255) / 256, 256>>>(features);
    k_fill_pe<<<(NN * 32 + 255) / 256, 256>>>(pe0, pos, 128);

    dim3 ggrid((256 + BN - 1) / BN, (NN + BM - 1) / BM);
    int attn_blocks = (NN * 4 + 7) / 8;
    int edge_blocks = (NN + 7) / 8;

    // layer 0
    k_gemm_tf32<<<ggrid, 256>>>(W0, 160);
    k_attn<<<attn_blocks, 256>>>(al0, ar0);
    k_edge<<<edge_blocks, 256>>>(out, 0);
    k_fill_pe<<<(NN * 32 + 255) / 256, 256>>>(pe1, pos, 256);

    // layer 1
    k_gemm_tf32<<<ggrid, 256>>>(W1, 288);
    k_attn<<<attn_blocks, 256>>>(al1, ar1);
    k_edge<<<edge_blocks, 256>>>(out, 0);
    k_fill_pe<<<(NN * 32 + 255) / 256, 256>>>(pe2, pos, 256);

    // layer 2
    k_gemm_tf32<<<ggrid, 256>>>(W2, 288);
    k_attn<<<attn_blocks, 256>>>(al2, ar2);
    k_edge<<<edge_blocks, 256>>>(out, 1);
}